// round 13
// baseline (speedup 1.0000x reference)
#include <cuda_runtime.h>
#include <cuda_bf16.h>
#include <cstdint>
#include <math.h>

// Problem constants
#define B_SZ   4
#define T_SEQ  1024
#define DMODEL 1024
#define NHEAD  16
#define HDIM   64
#define ROWS   (B_SZ * T_SEQ)          // 4096
#define QKVN   (3 * DMODEL)            // 3072
#define K3     3072                    // bf16x3 expanded K

// Scratch (__device__ globals; allocation-free rule)
__device__ float         g_qkv  [(size_t)ROWS  * QKVN];  // fp32 qkv [4096,3072]
__device__ __nv_bfloat16 g_xb   [(size_t)ROWS  * K3];    // x split   [hi|lo|hi]
__device__ __nv_bfloat16 g_attnb[(size_t)ROWS  * K3];    // attn out  [hi|lo|hi]
__device__ __nv_bfloat16 g_wqkvb[(size_t)QKVN  * K3];    // w_qkv^T   [hi|hi|lo]
__device__ __nv_bfloat16 g_woutb[(size_t)DMODEL* K3];    // w_out^T   [hi|hi|lo]

// ---------------------------------------------------------------------------
// Helpers (baseline PTX: ldmatrix / mma.sync / cp.async — sm_80+)
// ---------------------------------------------------------------------------
__device__ __forceinline__ uint32_t smem_u32(const void* p) {
    uint32_t a;
    asm("{ .reg .u64 t; cvta.to.shared.u64 t, %1; cvt.u32.u64 %0, t; }"
        : "=r"(a) : "l"(p));
    return a;
}

__device__ __forceinline__ void ldsm_x4(uint32_t* r, uint32_t addr) {
    asm volatile("ldmatrix.sync.aligned.m8n8.x4.shared.b16 {%0,%1,%2,%3}, [%4];"
                 : "=r"(r[0]), "=r"(r[1]), "=r"(r[2]), "=r"(r[3]) : "r"(addr));
}

__device__ __forceinline__ void mma16816(float* d, const uint32_t* a, const uint32_t* b) {
    asm volatile(
        "mma.sync.aligned.m16n8k16.row.col.f32.bf16.bf16.f32 "
        "{%0,%1,%2,%3}, {%4,%5,%6,%7}, {%8,%9}, {%0,%1,%2,%3};"
        : "+f"(d[0]), "+f"(d[1]), "+f"(d[2]), "+f"(d[3])
        : "r"(a[0]), "r"(a[1]), "r"(a[2]), "r"(a[3]), "r"(b[0]), "r"(b[1]));
}

__device__ __forceinline__ uint32_t pack2(__nv_bfloat16 a, __nv_bfloat16 b) {
    __nv_bfloat162 t; t.x = a; t.y = b;           // .x = low half (col 2i)
    return *(uint32_t*)&t;
}

#define CP_ASYNC16(dst, src) \
    asm volatile("cp.async.cg.shared.global [%0], [%1], 16;" :: "r"(dst), "l"(src))
#define CP_COMMIT() asm volatile("cp.async.commit_group;" ::: "memory")
#define CP_WAIT1()  asm volatile("cp.async.wait_group 1;" ::: "memory")
#define CP_WAIT0()  asm volatile("cp.async.wait_group 0;" ::: "memory")

// ---------------------------------------------------------------------------
// Conversion kernels: fp32 -> bf16 hi/lo split layouts
// ---------------------------------------------------------------------------
__global__ void __launch_bounds__(256) conv_act(
    const float* __restrict__ X, __nv_bfloat16* __restrict__ out)
{
    int idx = blockIdx.x * 256 + threadIdx.x;
    int row = idx >> 8;
    int c4  = (idx & 255) << 2;
    float4 v = *(const float4*)(X + (size_t)row * 1024 + c4);
    float vv[4] = {v.x, v.y, v.z, v.w};
    __nv_bfloat16 hi[4], lo[4];
#pragma unroll
    for (int j = 0; j < 4; j++) {
        hi[j] = __float2bfloat16(vv[j]);
        lo[j] = __float2bfloat16(vv[j] - __bfloat162float(hi[j]));
    }
    __nv_bfloat16* o = out + (size_t)row * K3 + c4;
    __nv_bfloat162 h01, h23, l01, l23;
    h01.x = hi[0]; h01.y = hi[1]; h23.x = hi[2]; h23.y = hi[3];
    l01.x = lo[0]; l01.y = lo[1]; l23.x = lo[2]; l23.y = lo[3];
    *(__nv_bfloat162*)(o)        = h01;  *(__nv_bfloat162*)(o + 2)    = h23;
    *(__nv_bfloat162*)(o + 1024) = l01;  *(__nv_bfloat162*)(o + 1026) = l23;
    *(__nv_bfloat162*)(o + 2048) = h01;  *(__nv_bfloat162*)(o + 2050) = h23;
}

__global__ void __launch_bounds__(256) conv_wt(
    const float* __restrict__ W, __nv_bfloat16* __restrict__ out, int N)
{
    __shared__ float tile[32][33];
    const int tx = threadIdx.x, ty = threadIdx.y;         // 32 x 8
    const int n0 = blockIdx.x * 32, k0 = blockIdx.y * 32;
#pragma unroll
    for (int i = 0; i < 4; i++)
        tile[ty + i * 8][tx] = W[(size_t)(k0 + ty + i * 8) * N + n0 + tx];
    __syncthreads();
#pragma unroll
    for (int i = 0; i < 4; i++) {
        int n = n0 + ty + i * 8;
        int k = k0 + tx;
        float v = tile[tx][ty + i * 8];
        __nv_bfloat16 hi = __float2bfloat16(v);
        __nv_bfloat16 lo = __float2bfloat16(v - __bfloat162float(hi));
        __nv_bfloat16* o = out + (size_t)n * K3 + k;
        o[0]    = hi;
        o[1024] = hi;
        o[2048] = lo;
    }
}

// ---------------------------------------------------------------------------
// HMMA GEMM: C[M,N] fp32 = A[M,K3](bf16,rm) x B[N,K3](bf16,rm)^T  (unchanged)
// ---------------------------------------------------------------------------
#define BM 128
#define BN 128
#define BKC 32
#define LDSS 40
#define NKB (K3 / BKC)

__global__ void __launch_bounds__(256) gemm_hmma(
    const __nv_bfloat16* __restrict__ A, const __nv_bfloat16* __restrict__ Bm,
    float* __restrict__ C, int N)
{
    __shared__ __nv_bfloat16 sA[2][BM * LDSS];
    __shared__ __nv_bfloat16 sB[2][BN * LDSS];

    const int t    = threadIdx.x;
    const int wid  = t >> 5, lane = t & 31;
    const int m0   = blockIdx.y * BM, n0 = blockIdx.x * BN;
    const int wm   = (wid & 1) * 64;
    const int wn   = (wid >> 1) * 32;

    const int lrow0 = t >> 2;
    const int lc    = t & 3;

    float acc[4][4][4];
#pragma unroll
    for (int i = 0; i < 4; i++)
#pragma unroll
        for (int j = 0; j < 4; j++)
#pragma unroll
            for (int r = 0; r < 4; r++) acc[i][j][r] = 0.f;

    const uint32_t sAu[2] = {smem_u32(&sA[0][0]), smem_u32(&sA[1][0])};
    const uint32_t sBu[2] = {smem_u32(&sB[0][0]), smem_u32(&sB[1][0])};

    {
        const size_t koff = lc * 8;
#pragma unroll
        for (int i = 0; i < 2; i++) {
            int r = lrow0 + i * 64;
            CP_ASYNC16(sAu[0] + (r * LDSS + lc * 8) * 2, A + (size_t)(m0 + r) * K3 + koff);
            CP_ASYNC16(sBu[0] + (r * LDSS + lc * 8) * 2, Bm + (size_t)(n0 + r) * K3 + koff);
        }
        CP_COMMIT();
    }

    for (int kb = 0; kb < NKB; kb++) {
        const int cur = kb & 1;
        if (kb + 1 < NKB) {
            const int nxt = cur ^ 1;
            const size_t koff = (size_t)(kb + 1) * BKC + lc * 8;
#pragma unroll
            for (int i = 0; i < 2; i++) {
                int r = lrow0 + i * 64;
                CP_ASYNC16(sAu[nxt] + (r * LDSS + lc * 8) * 2, A + (size_t)(m0 + r) * K3 + koff);
                CP_ASYNC16(sBu[nxt] + (r * LDSS + lc * 8) * 2, Bm + (size_t)(n0 + r) * K3 + koff);
            }
            CP_COMMIT();
            CP_WAIT1();
        } else {
            CP_WAIT0();
        }
        __syncthreads();

#pragma unroll
        for (int kh = 0; kh < 2; kh++) {
            const int k0 = kh * 16;
            uint32_t aF[4][4], bF[4][2];
            {
                const int rr = (lane & 15);
                const int cc = k0 + ((lane >> 4) << 3);
#pragma unroll
                for (int mt = 0; mt < 4; mt++)
                    ldsm_x4(aF[mt], sAu[cur] + (((wm + mt * 16 + rr) * LDSS + cc) << 1));
            }
            {
                const int rr = (lane & 7) + ((lane >> 1) & 8);
                const int cc = k0 + (lane & 8);
#pragma unroll
                for (int np = 0; np < 2; np++) {
                    uint32_t r4[4];
                    ldsm_x4(r4, sBu[cur] + (((wn + np * 16 + rr) * LDSS + cc) << 1));
                    bF[np * 2][0]     = r4[0];  bF[np * 2][1]     = r4[1];
                    bF[np * 2 + 1][0] = r4[2];  bF[np * 2 + 1][1] = r4[3];
                }
            }
#pragma unroll
            for (int mt = 0; mt < 4; mt++)
#pragma unroll
                for (int nt = 0; nt < 4; nt++)
                    mma16816(acc[mt][nt], aF[mt], bF[nt]);
        }
        __syncthreads();
    }

    const int er = lane >> 2, ec = (lane & 3) * 2;
#pragma unroll
    for (int mt = 0; mt < 4; mt++) {
#pragma unroll
        for (int nt = 0; nt < 4; nt++) {
            int r   = m0 + wm + mt * 16 + er;
            int col = n0 + wn + nt * 8 + ec;
            *(float2*)(C + (size_t)r * N + col)       = make_float2(acc[mt][nt][0], acc[mt][nt][1]);
            *(float2*)(C + (size_t)(r + 8) * N + col) = make_float2(acc[mt][nt][2], acc[mt][nt][3]);
        }
    }
}

// ---------------------------------------------------------------------------
// HMMA flash attention (causal).
// Grid: (16 qtiles, 64 bh). Block: 128 threads, 4 warps; warp owns 16 q-rows.
// S = Q'K'^T via bf16x3 split (K'=192). P@V via P hi/lo + V hi/lo (3 terms).
// Writes bf16x3 split output [hi|lo|hi] for the proj GEMM.
// ---------------------------------------------------------------------------
#define QSTR 200    // Q'/K' smem row stride in bf16 (100 words ≡ 4 mod 32)
#define VSTR 72     // Vt smem row stride in bf16   (36 words  ≡ 4 mod 32)
#define ATTN_SMEM (2 * 64 * QSTR * 2 + 2 * 64 * VSTR * 2)   // 69632 B

__global__ void __launch_bounds__(128) attn_hmma(
    const float* __restrict__ qkv, __nv_bfloat16* __restrict__ out)
{
    const int qt = (gridDim.x - 1) - blockIdx.x;   // heavy tiles first
    const int bh = blockIdx.y;
    const int b  = bh >> 4, h = bh & 15;

    extern __shared__ __nv_bfloat16 smb[];
    __nv_bfloat16* Qs  = smb;                   // [64][QSTR]  [Qhi|Qlo|Qhi]
    __nv_bfloat16* Ks  = Qs + 64 * QSTR;        // [64][QSTR]  [Khi|Khi|Klo]
    __nv_bfloat16* Vhi = Ks + 64 * QSTR;        // [hd=64][VSTR] transposed
    __nv_bfloat16* Vlo = Vhi + 64 * VSTR;

    const uint32_t Qu  = smem_u32(Qs),  Ku  = smem_u32(Ks);
    const uint32_t Vhu = smem_u32(Vhi), Vlu = smem_u32(Vlo);

    const int t = threadIdx.x, wid = t >> 5, lane = t & 31;
    const int wq = wid * 16;              // warp's q-row base within tile
    const int er = lane >> 2;             // 0..7
    const int qc = lane & 3;

    const float* base = qkv + (size_t)(b * T_SEQ) * QKVN;

    // ---- Load Q tile once: fp32 -> [hi|lo|hi] ----
    for (int i = t; i < 1024; i += 128) {
        int q = i >> 4, d4 = (i & 15) * 4;
        float4 v = *(const float4*)(base + (size_t)(qt * 64 + q) * QKVN + h * HDIM + d4);
        float f[4] = {v.x, v.y, v.z, v.w};
        __nv_bfloat16 hi[4], lo[4];
#pragma unroll
        for (int j = 0; j < 4; j++) {
            hi[j] = __float2bfloat16(f[j]);
            lo[j] = __float2bfloat16(f[j] - __bfloat162float(hi[j]));
        }
        __nv_bfloat162 h01, h23, l01, l23;
        h01.x = hi[0]; h01.y = hi[1]; h23.x = hi[2]; h23.y = hi[3];
        l01.x = lo[0]; l01.y = lo[1]; l23.x = lo[2]; l23.y = lo[3];
        __nv_bfloat16* r = Qs + q * QSTR + d4;
        *(__nv_bfloat162*)(r)           = h01;  *(__nv_bfloat162*)(r + 2)       = h23;
        *(__nv_bfloat162*)(r + 64)      = l01;  *(__nv_bfloat162*)(r + 66)      = l23;
        *(__nv_bfloat162*)(r + 128)     = h01;  *(__nv_bfloat162*)(r + 130)     = h23;
    }

    float m_i[2] = {-1e30f, -1e30f}, l_i[2] = {0.f, 0.f};
    float oacc[8][4];
#pragma unroll
    for (int nt = 0; nt < 8; nt++)
#pragma unroll
        for (int r = 0; r < 4; r++) oacc[nt][r] = 0.f;

    const int brr = (lane & 7) + ((lane >> 1) & 8);
    const int bcc = (lane & 8);
    const uint32_t arow = Qu + (((wq + (lane & 15)) * QSTR + ((lane >> 4) << 3)) << 1);

    for (int kt = 0; kt <= qt; kt++) {
        __syncthreads();
        // ---- Load K -> [hi|hi|lo], V -> transposed hi/lo ----
        for (int i = t; i < 1024; i += 128) {
            int k = i >> 4, d4 = (i & 15) * 4;
            float4 kv = *(const float4*)(base + (size_t)(kt * 64 + k) * QKVN + DMODEL + h * HDIM + d4);
            float kf[4] = {kv.x, kv.y, kv.z, kv.w};
            __nv_bfloat16 khi[4], klo[4];
#pragma unroll
            for (int j = 0; j < 4; j++) {
                khi[j] = __float2bfloat16(kf[j]);
                klo[j] = __float2bfloat16(kf[j] - __bfloat162float(khi[j]));
            }
            __nv_bfloat162 h01, h23, l01, l23;
            h01.x = khi[0]; h01.y = khi[1]; h23.x = khi[2]; h23.y = khi[3];
            l01.x = klo[0]; l01.y = klo[1]; l23.x = klo[2]; l23.y = klo[3];
            __nv_bfloat16* r = Ks + k * QSTR + d4;
            *(__nv_bfloat162*)(r)       = h01;  *(__nv_bfloat162*)(r + 2)   = h23;
            *(__nv_bfloat162*)(r + 64)  = h01;  *(__nv_bfloat162*)(r + 66)  = h23;
            *(__nv_bfloat162*)(r + 128) = l01;  *(__nv_bfloat162*)(r + 130) = l23;

            float4 vv = *(const float4*)(base + (size_t)(kt * 64 + k) * QKVN + 2 * DMODEL + h * HDIM + d4);
            float vf[4] = {vv.x, vv.y, vv.z, vv.w};
#pragma unroll
            for (int j = 0; j < 4; j++) {
                __nv_bfloat16 vh = __float2bfloat16(vf[j]);
                __nv_bfloat16 vl = __float2bfloat16(vf[j] - __bfloat162float(vh));
                Vhi[(d4 + j) * VSTR + k] = vh;
                Vlo[(d4 + j) * VSTR + k] = vl;
            }
        }
        __syncthreads();

        // ---- S = Q' K'^T (12 k16 chunks over K'=192) ----
        float sacc[8][4];
#pragma unroll
        for (int nt = 0; nt < 8; nt++)
#pragma unroll
            for (int r = 0; r < 4; r++) sacc[nt][r] = 0.f;

#pragma unroll
        for (int kc = 0; kc < 12; kc++) {
            uint32_t aF[4];
            ldsm_x4(aF, arow + (kc << 5));       // +kc*16 bf16 = 32 B
#pragma unroll
            for (int np = 0; np < 4; np++) {
                uint32_t r4[4];
                ldsm_x4(r4, Ku + (((np * 16 + brr) * QSTR + kc * 16 + bcc) << 1));
                mma16816(sacc[2 * np],     aF, r4);
                mma16816(sacc[2 * np + 1], aF, r4 + 2);
            }
        }

        const float scale = 0.125f;
#pragma unroll
        for (int nt = 0; nt < 8; nt++)
#pragma unroll
            for (int r = 0; r < 4; r++) sacc[nt][r] *= scale;

        if (kt == qt) {
            const int row0 = wq + er, row1 = row0 + 8;
#pragma unroll
            for (int nt = 0; nt < 8; nt++)
#pragma unroll
                for (int jj = 0; jj < 2; jj++) {
                    int col = nt * 8 + qc * 2 + jj;
                    if (col > row0) sacc[nt][jj]     = -1e30f;
                    if (col > row1) sacc[nt][2 + jj] = -1e30f;
                }
        }

        // ---- Online softmax (rows er, er+8; reduce over lane-quad) ----
        float mx0 = -1e30f, mx1 = -1e30f;
#pragma unroll
        for (int nt = 0; nt < 8; nt++) {
            mx0 = fmaxf(mx0, fmaxf(sacc[nt][0], sacc[nt][1]));
            mx1 = fmaxf(mx1, fmaxf(sacc[nt][2], sacc[nt][3]));
        }
#pragma unroll
        for (int o = 1; o < 4; o <<= 1) {
            mx0 = fmaxf(mx0, __shfl_xor_sync(0xffffffffu, mx0, o));
            mx1 = fmaxf(mx1, __shfl_xor_sync(0xffffffffu, mx1, o));
        }
        const float mn0 = fmaxf(m_i[0], mx0), mn1 = fmaxf(m_i[1], mx1);
        const float cf0 = __expf(m_i[0] - mn0), cf1 = __expf(m_i[1] - mn1);
        m_i[0] = mn0; m_i[1] = mn1;

        uint32_t aPhi[4][4], aPlo[4][4];
        float s0 = 0.f, s1 = 0.f;
#pragma unroll
        for (int c = 0; c < 4; c++) {
#pragma unroll
            for (int u = 0; u < 2; u++) {
                const int nt = 2 * c + u;
                float p0 = __expf(sacc[nt][0] - mn0);
                float p1 = __expf(sacc[nt][1] - mn0);
                float p2 = __expf(sacc[nt][2] - mn1);
                float p3 = __expf(sacc[nt][3] - mn1);
                s0 += p0 + p1;  s1 += p2 + p3;
                __nv_bfloat16 h0 = __float2bfloat16(p0), h1 = __float2bfloat16(p1);
                __nv_bfloat16 h2 = __float2bfloat16(p2), h3 = __float2bfloat16(p3);
                aPhi[c][2 * u]     = pack2(h0, h1);
                aPhi[c][2 * u + 1] = pack2(h2, h3);
                aPlo[c][2 * u]     = pack2(__float2bfloat16(p0 - __bfloat162float(h0)),
                                           __float2bfloat16(p1 - __bfloat162float(h1)));
                aPlo[c][2 * u + 1] = pack2(__float2bfloat16(p2 - __bfloat162float(h2)),
                                           __float2bfloat16(p3 - __bfloat162float(h3)));
            }
        }
#pragma unroll
        for (int o = 1; o < 4; o <<= 1) {
            s0 += __shfl_xor_sync(0xffffffffu, s0, o);
            s1 += __shfl_xor_sync(0xffffffffu, s1, o);
        }
        l_i[0] = l_i[0] * cf0 + s0;
        l_i[1] = l_i[1] * cf1 + s1;

#pragma unroll
        for (int nt = 0; nt < 8; nt++) {
            oacc[nt][0] *= cf0; oacc[nt][1] *= cf0;
            oacc[nt][2] *= cf1; oacc[nt][3] *= cf1;
        }

        // ---- O += Phi@Vhi + Plo@Vhi + Phi@Vlo ----
#pragma unroll
        for (int c = 0; c < 4; c++) {
#pragma unroll
            for (int np = 0; np < 4; np++) {
                uint32_t vh[4], vl[4];
                const uint32_t vo = (((np * 16 + brr) * VSTR + c * 16 + bcc) << 1);
                ldsm_x4(vh, Vhu + vo);
                ldsm_x4(vl, Vlu + vo);
                mma16816(oacc[2 * np],     aPhi[c], vh);
                mma16816(oacc[2 * np + 1], aPhi[c], vh + 2);
                mma16816(oacc[2 * np],     aPlo[c], vh);
                mma16816(oacc[2 * np + 1], aPlo[c], vh + 2);
                mma16816(oacc[2 * np],     aPhi[c], vl);
                mma16816(oacc[2 * np + 1], aPhi[c], vl + 2);
            }
        }
    }

    // ---- Epilogue: normalize, write bf16x3 split [hi|lo|hi] ----
    const float inv0 = 1.0f / l_i[0], inv1 = 1.0f / l_i[1];
    const int gr0 = b * T_SEQ + qt * 64 + wq + er;
    const int gr1 = gr0 + 8;
#pragma unroll
    for (int nt = 0; nt < 8; nt++) {
        const int col = h * HDIM + nt * 8 + qc * 2;
        float f0 = oacc[nt][0] * inv0, f1 = oacc[nt][1] * inv0;
        float f2 = oacc[nt][2] * inv1, f3 = oacc[nt][3] * inv1;
        __nv_bfloat16 h0 = __float2bfloat16(f0), h1 = __float2bfloat16(f1);
        __nv_bfloat16 h2 = __float2bfloat16(f2), h3 = __float2bfloat16(f3);
        __nv_bfloat162 hp0; hp0.x = h0; hp0.y = h1;
        __nv_bfloat162 hp1; hp1.x = h2; hp1.y = h3;
        __nv_bfloat162 lp0; lp0.x = __float2bfloat16(f0 - __bfloat162float(h0));
                            lp0.y = __float2bfloat16(f1 - __bfloat162float(h1));
        __nv_bfloat162 lp1; lp1.x = __float2bfloat16(f2 - __bfloat162float(h2));
                            lp1.y = __float2bfloat16(f3 - __bfloat162float(h3));
        __nv_bfloat16* o0 = out + (size_t)gr0 * K3 + col;
        __nv_bfloat16* o1 = out + (size_t)gr1 * K3 + col;
        *(__nv_bfloat162*)(o0)        = hp0;
        *(__nv_bfloat162*)(o0 + 1024) = lp0;
        *(__nv_bfloat162*)(o0 + 2048) = hp0;
        *(__nv_bfloat162*)(o1)        = hp1;
        *(__nv_bfloat162*)(o1 + 1024) = lp1;
        *(__nv_bfloat162*)(o1 + 2048) = hp1;
    }
}

// ---------------------------------------------------------------------------
extern "C" void kernel_launch(void* const* d_in, const int* in_sizes, int n_in,
                              void* d_out, int out_size)
{
    const float* x     = (const float*)d_in[0];
    // d_in[1] = mask (causal, applied analytically)
    const float* w_qkv = (const float*)d_in[2];
    const float* w_out = (const float*)d_in[3];
    float* out = (float*)d_out;

    float *qkv_ptr;
    __nv_bfloat16 *xb, *attnb, *wqkvb, *woutb;
    cudaGetSymbolAddress((void**)&qkv_ptr, g_qkv);
    cudaGetSymbolAddress((void**)&xb,     g_xb);
    cudaGetSymbolAddress((void**)&attnb,  g_attnb);
    cudaGetSymbolAddress((void**)&wqkvb,  g_wqkvb);
    cudaGetSymbolAddress((void**)&woutb,  g_woutb);

    cudaFuncSetAttribute(attn_hmma,
                         cudaFuncAttributeMaxDynamicSharedMemorySize, ATTN_SMEM);

    // 1) Split conversions
    conv_act<<<ROWS, 256>>>(x, xb);
    conv_wt <<<dim3(QKVN / 32, 32), dim3(32, 8)>>>(w_qkv, wqkvb, QKVN);
    conv_wt <<<dim3(DMODEL / 32, 32), dim3(32, 8)>>>(w_out, woutb, DMODEL);

    // 2) QKV projection
    gemm_hmma<<<dim3(QKVN / BN, ROWS / BM), 256>>>(xb, wqkvb, qkv_ptr, QKVN);

    // 3) HMMA flash attention (writes split bf16 output)
    attn_hmma<<<dim3(T_SEQ / 64, B_SZ * NHEAD), 128, ATTN_SMEM>>>(qkv_ptr, attnb);

    // 4) Output projection
    gemm_hmma<<<dim3(DMODEL / BN, ROWS / BM), 256>>>(attnb, woutb, out, DMODEL);
}

// round 14
// speedup vs baseline: 1.0052x; 1.0052x over previous
#include <cuda_runtime.h>
#include <cuda_bf16.h>
#include <cstdint>
#include <math.h>

// Problem constants
#define B_SZ   4
#define T_SEQ  1024
#define DMODEL 1024
#define NHEAD  16
#define HDIM   64
#define ROWS   (B_SZ * T_SEQ)          // 4096
#define QKVN   (3 * DMODEL)            // 3072
#define K3     3072                    // bf16x3 expanded K

// Scratch (__device__ globals; allocation-free rule)
__device__ float         g_qkv  [(size_t)ROWS  * QKVN];  // fp32 qkv [4096,3072]
__device__ __nv_bfloat16 g_xb   [(size_t)ROWS  * K3];    // x split   [hi|lo|hi]
__device__ __nv_bfloat16 g_attnb[(size_t)ROWS  * K3];    // attn out  [hi|lo|hi]
__device__ __nv_bfloat16 g_wqkvb[(size_t)QKVN  * K3];    // w_qkv^T   [hi|hi|lo]
__device__ __nv_bfloat16 g_woutb[(size_t)DMODEL* K3];    // w_out^T   [hi|hi|lo]

// ---------------------------------------------------------------------------
// Helpers (baseline PTX: ldmatrix / mma.sync / cp.async — sm_80+)
// ---------------------------------------------------------------------------
__device__ __forceinline__ uint32_t smem_u32(const void* p) {
    uint32_t a;
    asm("{ .reg .u64 t; cvta.to.shared.u64 t, %1; cvt.u32.u64 %0, t; }"
        : "=r"(a) : "l"(p));
    return a;
}

__device__ __forceinline__ void ldsm_x4(uint32_t* r, uint32_t addr) {
    asm volatile("ldmatrix.sync.aligned.m8n8.x4.shared.b16 {%0,%1,%2,%3}, [%4];"
                 : "=r"(r[0]), "=r"(r[1]), "=r"(r[2]), "=r"(r[3]) : "r"(addr));
}

__device__ __forceinline__ void mma16816(float* d, const uint32_t* a, const uint32_t* b) {
    asm volatile(
        "mma.sync.aligned.m16n8k16.row.col.f32.bf16.bf16.f32 "
        "{%0,%1,%2,%3}, {%4,%5,%6,%7}, {%8,%9}, {%0,%1,%2,%3};"
        : "+f"(d[0]), "+f"(d[1]), "+f"(d[2]), "+f"(d[3])
        : "r"(a[0]), "r"(a[1]), "r"(a[2]), "r"(a[3]), "r"(b[0]), "r"(b[1]));
}

__device__ __forceinline__ uint32_t pack2(__nv_bfloat16 a, __nv_bfloat16 b) {
    __nv_bfloat162 t; t.x = a; t.y = b;           // .x = low half (col 2i)
    return *(uint32_t*)&t;
}

#define CP_ASYNC16(dst, src) \
    asm volatile("cp.async.cg.shared.global [%0], [%1], 16;" :: "r"(dst), "l"(src))
#define CP_COMMIT() asm volatile("cp.async.commit_group;" ::: "memory")
#define CP_WAIT1()  asm volatile("cp.async.wait_group 1;" ::: "memory")
#define CP_WAIT0()  asm volatile("cp.async.wait_group 0;" ::: "memory")

// ---------------------------------------------------------------------------
// Conversion kernels: fp32 -> bf16 hi/lo split layouts
// ---------------------------------------------------------------------------
__global__ void __launch_bounds__(256) conv_act(
    const float* __restrict__ X, __nv_bfloat16* __restrict__ out)
{
    int idx = blockIdx.x * 256 + threadIdx.x;
    int row = idx >> 8;
    int c4  = (idx & 255) << 2;
    float4 v = *(const float4*)(X + (size_t)row * 1024 + c4);
    float vv[4] = {v.x, v.y, v.z, v.w};
    __nv_bfloat16 hi[4], lo[4];
#pragma unroll
    for (int j = 0; j < 4; j++) {
        hi[j] = __float2bfloat16(vv[j]);
        lo[j] = __float2bfloat16(vv[j] - __bfloat162float(hi[j]));
    }
    __nv_bfloat16* o = out + (size_t)row * K3 + c4;
    __nv_bfloat162 h01, h23, l01, l23;
    h01.x = hi[0]; h01.y = hi[1]; h23.x = hi[2]; h23.y = hi[3];
    l01.x = lo[0]; l01.y = lo[1]; l23.x = lo[2]; l23.y = lo[3];
    *(__nv_bfloat162*)(o)        = h01;  *(__nv_bfloat162*)(o + 2)    = h23;
    *(__nv_bfloat162*)(o + 1024) = l01;  *(__nv_bfloat162*)(o + 1026) = l23;
    *(__nv_bfloat162*)(o + 2048) = h01;  *(__nv_bfloat162*)(o + 2050) = h23;
}

__global__ void __launch_bounds__(256) conv_wt(
    const float* __restrict__ W, __nv_bfloat16* __restrict__ out, int N)
{
    __shared__ float tile[32][33];
    const int tx = threadIdx.x, ty = threadIdx.y;         // 32 x 8
    const int n0 = blockIdx.x * 32, k0 = blockIdx.y * 32;
#pragma unroll
    for (int i = 0; i < 4; i++)
        tile[ty + i * 8][tx] = W[(size_t)(k0 + ty + i * 8) * N + n0 + tx];
    __syncthreads();
#pragma unroll
    for (int i = 0; i < 4; i++) {
        int n = n0 + ty + i * 8;
        int k = k0 + tx;
        float v = tile[tx][ty + i * 8];
        __nv_bfloat16 hi = __float2bfloat16(v);
        __nv_bfloat16 lo = __float2bfloat16(v - __bfloat162float(hi));
        __nv_bfloat16* o = out + (size_t)n * K3 + k;
        o[0]    = hi;
        o[1024] = hi;
        o[2048] = lo;
    }
}

// ---------------------------------------------------------------------------
// HMMA GEMM: C[M,N] fp32 = A[M,K3](bf16,rm) x B[N,K3](bf16,rm)^T  (unchanged)
// ---------------------------------------------------------------------------
#define BM 128
#define BN 128
#define BKC 32
#define LDSS 40
#define NKB (K3 / BKC)

__global__ void __launch_bounds__(256) gemm_hmma(
    const __nv_bfloat16* __restrict__ A, const __nv_bfloat16* __restrict__ Bm,
    float* __restrict__ C, int N)
{
    __shared__ __nv_bfloat16 sA[2][BM * LDSS];
    __shared__ __nv_bfloat16 sB[2][BN * LDSS];

    const int t    = threadIdx.x;
    const int wid  = t >> 5, lane = t & 31;
    const int m0   = blockIdx.y * BM, n0 = blockIdx.x * BN;
    const int wm   = (wid & 1) * 64;
    const int wn   = (wid >> 1) * 32;

    const int lrow0 = t >> 2;
    const int lc    = t & 3;

    float acc[4][4][4];
#pragma unroll
    for (int i = 0; i < 4; i++)
#pragma unroll
        for (int j = 0; j < 4; j++)
#pragma unroll
            for (int r = 0; r < 4; r++) acc[i][j][r] = 0.f;

    const uint32_t sAu[2] = {smem_u32(&sA[0][0]), smem_u32(&sA[1][0])};
    const uint32_t sBu[2] = {smem_u32(&sB[0][0]), smem_u32(&sB[1][0])};

    {
        const size_t koff = lc * 8;
#pragma unroll
        for (int i = 0; i < 2; i++) {
            int r = lrow0 + i * 64;
            CP_ASYNC16(sAu[0] + (r * LDSS + lc * 8) * 2, A + (size_t)(m0 + r) * K3 + koff);
            CP_ASYNC16(sBu[0] + (r * LDSS + lc * 8) * 2, Bm + (size_t)(n0 + r) * K3 + koff);
        }
        CP_COMMIT();
    }

    for (int kb = 0; kb < NKB; kb++) {
        const int cur = kb & 1;
        if (kb + 1 < NKB) {
            const int nxt = cur ^ 1;
            const size_t koff = (size_t)(kb + 1) * BKC + lc * 8;
#pragma unroll
            for (int i = 0; i < 2; i++) {
                int r = lrow0 + i * 64;
                CP_ASYNC16(sAu[nxt] + (r * LDSS + lc * 8) * 2, A + (size_t)(m0 + r) * K3 + koff);
                CP_ASYNC16(sBu[nxt] + (r * LDSS + lc * 8) * 2, Bm + (size_t)(n0 + r) * K3 + koff);
            }
            CP_COMMIT();
            CP_WAIT1();
        } else {
            CP_WAIT0();
        }
        __syncthreads();

#pragma unroll
        for (int kh = 0; kh < 2; kh++) {
            const int k0 = kh * 16;
            uint32_t aF[4][4], bF[4][2];
            {
                const int rr = (lane & 15);
                const int cc = k0 + ((lane >> 4) << 3);
#pragma unroll
                for (int mt = 0; mt < 4; mt++)
                    ldsm_x4(aF[mt], sAu[cur] + (((wm + mt * 16 + rr) * LDSS + cc) << 1));
            }
            {
                const int rr = (lane & 7) + ((lane >> 1) & 8);
                const int cc = k0 + (lane & 8);
#pragma unroll
                for (int np = 0; np < 2; np++) {
                    uint32_t r4[4];
                    ldsm_x4(r4, sBu[cur] + (((wn + np * 16 + rr) * LDSS + cc) << 1));
                    bF[np * 2][0]     = r4[0];  bF[np * 2][1]     = r4[1];
                    bF[np * 2 + 1][0] = r4[2];  bF[np * 2 + 1][1] = r4[3];
                }
            }
#pragma unroll
            for (int mt = 0; mt < 4; mt++)
#pragma unroll
                for (int nt = 0; nt < 4; nt++)
                    mma16816(acc[mt][nt], aF[mt], bF[nt]);
        }
        __syncthreads();
    }

    const int er = lane >> 2, ec = (lane & 3) * 2;
#pragma unroll
    for (int mt = 0; mt < 4; mt++) {
#pragma unroll
        for (int nt = 0; nt < 4; nt++) {
            int r   = m0 + wm + mt * 16 + er;
            int col = n0 + wn + nt * 8 + ec;
            *(float2*)(C + (size_t)r * N + col)       = make_float2(acc[mt][nt][0], acc[mt][nt][1]);
            *(float2*)(C + (size_t)(r + 8) * N + col) = make_float2(acc[mt][nt][2], acc[mt][nt][3]);
        }
    }
}

// ---------------------------------------------------------------------------
// HMMA flash attention (causal).
// Grid: (16 qtiles, 64 bh). Block: 128 threads, 4 warps; warp owns 16 q-rows.
// S = Q'K'^T via bf16x3 split (K'=192). P@V via P hi/lo + V hi/lo (3 terms).
// Writes bf16x3 split output [hi|lo|hi] for the proj GEMM.
// ---------------------------------------------------------------------------
#define QSTR 200    // Q'/K' smem row stride in bf16 (100 words ≡ 4 mod 32)
#define VSTR 72     // Vt smem row stride in bf16   (36 words  ≡ 4 mod 32)
#define ATTN_SMEM (2 * 64 * QSTR * 2 + 2 * 64 * VSTR * 2)   // 69632 B

__global__ void __launch_bounds__(128) attn_hmma(
    const float* __restrict__ qkv, __nv_bfloat16* __restrict__ out)
{
    const int qt = (gridDim.x - 1) - blockIdx.x;   // heavy tiles first
    const int bh = blockIdx.y;
    const int b  = bh >> 4, h = bh & 15;

    extern __shared__ __nv_bfloat16 smb[];
    __nv_bfloat16* Qs  = smb;                   // [64][QSTR]  [Qhi|Qlo|Qhi]
    __nv_bfloat16* Ks  = Qs + 64 * QSTR;        // [64][QSTR]  [Khi|Khi|Klo]
    __nv_bfloat16* Vhi = Ks + 64 * QSTR;        // [hd=64][VSTR] transposed
    __nv_bfloat16* Vlo = Vhi + 64 * VSTR;

    const uint32_t Qu  = smem_u32(Qs),  Ku  = smem_u32(Ks);
    const uint32_t Vhu = smem_u32(Vhi), Vlu = smem_u32(Vlo);

    const int t = threadIdx.x, wid = t >> 5, lane = t & 31;
    const int wq = wid * 16;              // warp's q-row base within tile
    const int er = lane >> 2;             // 0..7
    const int qc = lane & 3;

    const float* base = qkv + (size_t)(b * T_SEQ) * QKVN;

    // ---- Load Q tile once: fp32 -> [hi|lo|hi] ----
    for (int i = t; i < 1024; i += 128) {
        int q = i >> 4, d4 = (i & 15) * 4;
        float4 v = *(const float4*)(base + (size_t)(qt * 64 + q) * QKVN + h * HDIM + d4);
        float f[4] = {v.x, v.y, v.z, v.w};
        __nv_bfloat16 hi[4], lo[4];
#pragma unroll
        for (int j = 0; j < 4; j++) {
            hi[j] = __float2bfloat16(f[j]);
            lo[j] = __float2bfloat16(f[j] - __bfloat162float(hi[j]));
        }
        __nv_bfloat162 h01, h23, l01, l23;
        h01.x = hi[0]; h01.y = hi[1]; h23.x = hi[2]; h23.y = hi[3];
        l01.x = lo[0]; l01.y = lo[1]; l23.x = lo[2]; l23.y = lo[3];
        __nv_bfloat16* r = Qs + q * QSTR + d4;
        *(__nv_bfloat162*)(r)           = h01;  *(__nv_bfloat162*)(r + 2)       = h23;
        *(__nv_bfloat162*)(r + 64)      = l01;  *(__nv_bfloat162*)(r + 66)      = l23;
        *(__nv_bfloat162*)(r + 128)     = h01;  *(__nv_bfloat162*)(r + 130)     = h23;
    }

    float m_i[2] = {-1e30f, -1e30f}, l_i[2] = {0.f, 0.f};
    float oacc[8][4];
#pragma unroll
    for (int nt = 0; nt < 8; nt++)
#pragma unroll
        for (int r = 0; r < 4; r++) oacc[nt][r] = 0.f;

    const int brr = (lane & 7) + ((lane >> 1) & 8);
    const int bcc = (lane & 8);
    const uint32_t arow = Qu + (((wq + (lane & 15)) * QSTR + ((lane >> 4) << 3)) << 1);

    for (int kt = 0; kt <= qt; kt++) {
        __syncthreads();
        // ---- Load K -> [hi|hi|lo], V -> transposed hi/lo ----
        for (int i = t; i < 1024; i += 128) {
            int k = i >> 4, d4 = (i & 15) * 4;
            float4 kv = *(const float4*)(base + (size_t)(kt * 64 + k) * QKVN + DMODEL + h * HDIM + d4);
            float kf[4] = {kv.x, kv.y, kv.z, kv.w};
            __nv_bfloat16 khi[4], klo[4];
#pragma unroll
            for (int j = 0; j < 4; j++) {
                khi[j] = __float2bfloat16(kf[j]);
                klo[j] = __float2bfloat16(kf[j] - __bfloat162float(khi[j]));
            }
            __nv_bfloat162 h01, h23, l01, l23;
            h01.x = khi[0]; h01.y = khi[1]; h23.x = khi[2]; h23.y = khi[3];
            l01.x = klo[0]; l01.y = klo[1]; l23.x = klo[2]; l23.y = klo[3];
            __nv_bfloat16* r = Ks + k * QSTR + d4;
            *(__nv_bfloat162*)(r)       = h01;  *(__nv_bfloat162*)(r + 2)   = h23;
            *(__nv_bfloat162*)(r + 64)  = h01;  *(__nv_bfloat162*)(r + 66)  = h23;
            *(__nv_bfloat162*)(r + 128) = l01;  *(__nv_bfloat162*)(r + 130) = l23;

            float4 vv = *(const float4*)(base + (size_t)(kt * 64 + k) * QKVN + 2 * DMODEL + h * HDIM + d4);
            float vf[4] = {vv.x, vv.y, vv.z, vv.w};
#pragma unroll
            for (int j = 0; j < 4; j++) {
                __nv_bfloat16 vh = __float2bfloat16(vf[j]);
                __nv_bfloat16 vl = __float2bfloat16(vf[j] - __bfloat162float(vh));
                Vhi[(d4 + j) * VSTR + k] = vh;
                Vlo[(d4 + j) * VSTR + k] = vl;
            }
        }
        __syncthreads();

        // ---- S = Q' K'^T (12 k16 chunks over K'=192) ----
        float sacc[8][4];
#pragma unroll
        for (int nt = 0; nt < 8; nt++)
#pragma unroll
            for (int r = 0; r < 4; r++) sacc[nt][r] = 0.f;

#pragma unroll
        for (int kc = 0; kc < 12; kc++) {
            uint32_t aF[4];
            ldsm_x4(aF, arow + (kc << 5));       // +kc*16 bf16 = 32 B
#pragma unroll
            for (int np = 0; np < 4; np++) {
                uint32_t r4[4];
                ldsm_x4(r4, Ku + (((np * 16 + brr) * QSTR + kc * 16 + bcc) << 1));
                mma16816(sacc[2 * np],     aF, r4);
                mma16816(sacc[2 * np + 1], aF, r4 + 2);
            }
        }

        const float scale = 0.125f;
#pragma unroll
        for (int nt = 0; nt < 8; nt++)
#pragma unroll
            for (int r = 0; r < 4; r++) sacc[nt][r] *= scale;

        if (kt == qt) {
            const int row0 = wq + er, row1 = row0 + 8;
#pragma unroll
            for (int nt = 0; nt < 8; nt++)
#pragma unroll
                for (int jj = 0; jj < 2; jj++) {
                    int col = nt * 8 + qc * 2 + jj;
                    if (col > row0) sacc[nt][jj]     = -1e30f;
                    if (col > row1) sacc[nt][2 + jj] = -1e30f;
                }
        }

        // ---- Online softmax (rows er, er+8; reduce over lane-quad) ----
        float mx0 = -1e30f, mx1 = -1e30f;
#pragma unroll
        for (int nt = 0; nt < 8; nt++) {
            mx0 = fmaxf(mx0, fmaxf(sacc[nt][0], sacc[nt][1]));
            mx1 = fmaxf(mx1, fmaxf(sacc[nt][2], sacc[nt][3]));
        }
#pragma unroll
        for (int o = 1; o < 4; o <<= 1) {
            mx0 = fmaxf(mx0, __shfl_xor_sync(0xffffffffu, mx0, o));
            mx1 = fmaxf(mx1, __shfl_xor_sync(0xffffffffu, mx1, o));
        }
        const float mn0 = fmaxf(m_i[0], mx0), mn1 = fmaxf(m_i[1], mx1);
        const float cf0 = __expf(m_i[0] - mn0), cf1 = __expf(m_i[1] - mn1);
        m_i[0] = mn0; m_i[1] = mn1;

        uint32_t aPhi[4][4], aPlo[4][4];
        float s0 = 0.f, s1 = 0.f;
#pragma unroll
        for (int c = 0; c < 4; c++) {
#pragma unroll
            for (int u = 0; u < 2; u++) {
                const int nt = 2 * c + u;
                float p0 = __expf(sacc[nt][0] - mn0);
                float p1 = __expf(sacc[nt][1] - mn0);
                float p2 = __expf(sacc[nt][2] - mn1);
                float p3 = __expf(sacc[nt][3] - mn1);
                s0 += p0 + p1;  s1 += p2 + p3;
                __nv_bfloat16 h0 = __float2bfloat16(p0), h1 = __float2bfloat16(p1);
                __nv_bfloat16 h2 = __float2bfloat16(p2), h3 = __float2bfloat16(p3);
                aPhi[c][2 * u]     = pack2(h0, h1);
                aPhi[c][2 * u + 1] = pack2(h2, h3);
                aPlo[c][2 * u]     = pack2(__float2bfloat16(p0 - __bfloat162float(h0)),
                                           __float2bfloat16(p1 - __bfloat162float(h1)));
                aPlo[c][2 * u + 1] = pack2(__float2bfloat16(p2 - __bfloat162float(h2)),
                                           __float2bfloat16(p3 - __bfloat162float(h3)));
            }
        }
#pragma unroll
        for (int o = 1; o < 4; o <<= 1) {
            s0 += __shfl_xor_sync(0xffffffffu, s0, o);
            s1 += __shfl_xor_sync(0xffffffffu, s1, o);
        }
        l_i[0] = l_i[0] * cf0 + s0;
        l_i[1] = l_i[1] * cf1 + s1;

#pragma unroll
        for (int nt = 0; nt < 8; nt++) {
            oacc[nt][0] *= cf0; oacc[nt][1] *= cf0;
            oacc[nt][2] *= cf1; oacc[nt][3] *= cf1;
        }

        // ---- O += Phi@Vhi + Plo@Vhi + Phi@Vlo ----
#pragma unroll
        for (int c = 0; c < 4; c++) {
#pragma unroll
            for (int np = 0; np < 4; np++) {
                uint32_t vh[4], vl[4];
                const uint32_t vo = (((np * 16 + brr) * VSTR + c * 16 + bcc) << 1);
                ldsm_x4(vh, Vhu + vo);
                ldsm_x4(vl, Vlu + vo);
                mma16816(oacc[2 * np],     aPhi[c], vh);
                mma16816(oacc[2 * np + 1], aPhi[c], vh + 2);
                mma16816(oacc[2 * np],     aPlo[c], vh);
                mma16816(oacc[2 * np + 1], aPlo[c], vh + 2);
                mma16816(oacc[2 * np],     aPhi[c], vl);
                mma16816(oacc[2 * np + 1], aPhi[c], vl + 2);
            }
        }
    }

    // ---- Epilogue: normalize, write bf16x3 split [hi|lo|hi] ----
    const float inv0 = 1.0f / l_i[0], inv1 = 1.0f / l_i[1];
    const int gr0 = b * T_SEQ + qt * 64 + wq + er;
    const int gr1 = gr0 + 8;
#pragma unroll
    for (int nt = 0; nt < 8; nt++) {
        const int col = h * HDIM + nt * 8 + qc * 2;
        float f0 = oacc[nt][0] * inv0, f1 = oacc[nt][1] * inv0;
        float f2 = oacc[nt][2] * inv1, f3 = oacc[nt][3] * inv1;
        __nv_bfloat16 h0 = __float2bfloat16(f0), h1 = __float2bfloat16(f1);
        __nv_bfloat16 h2 = __float2bfloat16(f2), h3 = __float2bfloat16(f3);
        __nv_bfloat162 hp0; hp0.x = h0; hp0.y = h1;
        __nv_bfloat162 hp1; hp1.x = h2; hp1.y = h3;
        __nv_bfloat162 lp0; lp0.x = __float2bfloat16(f0 - __bfloat162float(h0));
                            lp0.y = __float2bfloat16(f1 - __bfloat162float(h1));
        __nv_bfloat162 lp1; lp1.x = __float2bfloat16(f2 - __bfloat162float(h2));
                            lp1.y = __float2bfloat16(f3 - __bfloat162float(h3));
        __nv_bfloat16* o0 = out + (size_t)gr0 * K3 + col;
        __nv_bfloat16* o1 = out + (size_t)gr1 * K3 + col;
        *(__nv_bfloat162*)(o0)        = hp0;
        *(__nv_bfloat162*)(o0 + 1024) = lp0;
        *(__nv_bfloat162*)(o0 + 2048) = hp0;
        *(__nv_bfloat162*)(o1)        = hp1;
        *(__nv_bfloat162*)(o1 + 1024) = lp1;
        *(__nv_bfloat162*)(o1 + 2048) = hp1;
    }
}

// ---------------------------------------------------------------------------
extern "C" void kernel_launch(void* const* d_in, const int* in_sizes, int n_in,
                              void* d_out, int out_size)
{
    const float* x     = (const float*)d_in[0];
    // d_in[1] = mask (causal, applied analytically)
    const float* w_qkv = (const float*)d_in[2];
    const float* w_out = (const float*)d_in[3];
    float* out = (float*)d_out;

    float *qkv_ptr;
    __nv_bfloat16 *xb, *attnb, *wqkvb, *woutb;
    cudaGetSymbolAddress((void**)&qkv_ptr, g_qkv);
    cudaGetSymbolAddress((void**)&xb,     g_xb);
    cudaGetSymbolAddress((void**)&attnb,  g_attnb);
    cudaGetSymbolAddress((void**)&wqkvb,  g_wqkvb);
    cudaGetSymbolAddress((void**)&woutb,  g_woutb);

    cudaFuncSetAttribute(attn_hmma,
                         cudaFuncAttributeMaxDynamicSharedMemorySize, ATTN_SMEM);

    // 1) Split conversions
    conv_act<<<ROWS, 256>>>(x, xb);
    conv_wt <<<dim3(QKVN / 32, 32), dim3(32, 8)>>>(w_qkv, wqkvb, QKVN);
    conv_wt <<<dim3(DMODEL / 32, 32), dim3(32, 8)>>>(w_out, woutb, DMODEL);

    // 2) QKV projection
    gemm_hmma<<<dim3(QKVN / BN, ROWS / BM), 256>>>(xb, wqkvb, qkv_ptr, QKVN);

    // 3) HMMA flash attention (writes split bf16 output)
    attn_hmma<<<dim3(T_SEQ / 64, B_SZ * NHEAD), 128, ATTN_SMEM>>>(qkv_ptr, attnb);

    // 4) Output projection
    gemm_hmma<<<dim3(DMODEL / BN, ROWS / BM), 256>>>(attnb, woutb, out, DMODEL);
}